// round 11
// baseline (speedup 1.0000x reference)
#include <cuda_runtime.h>
#include <math_constants.h>

#define NB 50
#define S51 51
#define BATCH 4096
#define NFEAT 100
#define ALPHA_INV (1.0f/0.9f)

#define TPB   320            // threads per eval block
#define EPB   (2*TPB)        // evals per block = 640
#define TOT0  (BATCH*52)     // 212992
#define TOT1  (BATCH*51)     // 208896
#define NBLK0 333            // ceil(212992/640)
#define NBLK1 327            // ceil(208896/640)

// ---------------- device globals (scratch) ----------------------------------
__device__ float g_xm[BATCH];
__device__ float g_x[BATCH];
__device__ float g_x2[BATCH];
__device__ float g_xfinal;
__device__ float g_ccw[S51];
__device__ float g_ccs[S51];
__device__ float g_vals[2][BATCH * 52];   // [mode][row*52+slot]

// ---------------- packed f32x2 helpers --------------------------------------
__device__ __forceinline__ unsigned long long fma2(unsigned long long a,
                                                   unsigned long long b,
                                                   unsigned long long c) {
    unsigned long long d;
    asm("fma.rn.f32x2 %0, %1, %2, %3;" : "=l"(d) : "l"(a), "l"(b), "l"(c));
    return d;
}
__device__ __forceinline__ unsigned long long pack2(float lo, float hi) {
    unsigned long long d;
    asm("mov.b64 %0, {%1, %2};" : "=l"(d) : "f"(lo), "f"(hi));
    return d;
}
__device__ __forceinline__ void unpack2(unsigned long long v, float& lo, float& hi) {
    asm("mov.b64 {%0, %1}, %2;" : "=f"(lo), "=f"(hi) : "l"(v));
}

// ---------------- SMEM layout (floats) ----------------------------------------
// Act buffer: [65 rows][320 thread-cols] packed (aA,aB) u64; row 64 = prefetch pad.
#define ACT_ROW 640
#define OFF_ACT  0            // 65*640 = 41600 floats
#define OFF_W1T  41600        // transposed W1: [k][j], 4096 floats
#define OFF_W2T  45696        // transposed W2
#define OFF_W0   49792        // [64][8]: 5 weights + bias (+2 pad)
#define OFF_B1   50304
#define OFF_B2   50368
#define OFF_W3D  50432        // dup pairs (w3,w3): 128 floats
#define OFF_WF   50560        // 5
#define OFF_B3   50565
#define SMEM_FLOATS 50566
#define SMEM_BYTES (SMEM_FLOATS * 4)   // 202264 B

// ---------------- CC weights (fp64 on device) --------------------------------
__global__ void k_init_cc() {
    int j = threadIdx.x;
    if (j > NB) return;
    double s = 0.0;
    for (int i = 0; i <= NB; ++i) {
        double w;
        if (i & 1)        w = 0.0;
        else if (i == 0)  w = 1.0;
        else              w = 2.0 / (1.0 - (double)i * (double)i);
        double l;
        if (j == 0) l = 0.5;
        else {
            l = cos((double)i * (double)j * CUDART_PI / (double)NB);
            if (j == NB) l *= 0.5;
        }
        l *= 2.0 / (double)NB;
        s += l * w;
    }
    g_ccw[j] = (float)s;
    g_ccs[j] = (float)cos((double)j * CUDART_PI / (double)NB);
}

// ---------------- xm = x_ @ log_weight ----------------------------------------
__global__ void k_xm(const float* __restrict__ x_, const float* __restrict__ lw) {
    int warp = (blockIdx.x * blockDim.x + threadIdx.x) >> 5;
    int lane = threadIdx.x & 31;
    if (warp >= BATCH) return;
    const float* row = x_ + (size_t)warp * NFEAT;
    float p = 0.f;
    for (int j = lane; j < NFEAT; j += 32) p = fmaf(row[j], lw[j], p);
    #pragma unroll
    for (int off = 16; off; off >>= 1) p += __shfl_xor_sync(0xffffffffu, p, off);
    if (lane == 0) g_xm[warp] = p;
}

// ---------------- per-step prep ------------------------------------------------
__global__ void k_prep(const float* __restrict__ sp, const float* __restrict__ out, int step) {
    __shared__ float smax[1024];
    int tid = threadIdx.x;
    float lam = 1.f / (1.f + __expf(-sp[0]));
    float lmax = -CUDART_INF_F;
    for (int b = tid; b < BATCH; b += 1024) {
        float I1v = step ? out[b]             : 0.f;
        float I2v = step ? out[2 * BATCH + b] : 0.f;
        float xmv = g_xm[b];
        g_x[b]  = (1.f - lam) * xmv + lam * I1v;
        float x2v = (1.f - lam) * xmv + lam * I2v;
        g_x2[b] = x2v;
        lmax = fmaxf(lmax, x2v);
    }
    smax[tid] = lmax;
    __syncthreads();
    for (int off = 512; off; off >>= 1) {
        if (tid < off) smax[tid] = fmaxf(smax[tid], smax[tid + off]);
        __syncthreads();
    }
    if (tid == 0) g_xfinal = smax[0] + 10.f;
}

// ---------------- 64->64 layer for 2 packed evals, pipelined act path ----------
__device__ __forceinline__ void layer64x2(const float* __restrict__ sWT,
                                          const float* __restrict__ sbias,
                                          float* __restrict__ sActCol) {
    unsigned long long acc0[32], acc1[32];
    #pragma unroll
    for (int jp = 0; jp < 32; ++jp) {
        unsigned long long bp = *(const unsigned long long*)(sbias + 2 * jp);
        acc0[jp] = bp;
        acc1[jp] = bp;
    }

    unsigned long long apn = *(const unsigned long long*)(sActCol);   // k=0

    #pragma unroll 2
    for (int k = 0; k < 64; ++k) {
        float aA, aB;
        unpack2(apn, aA, aB);
        unsigned long long a2A = pack2(aA, aA);
        unsigned long long a2B = pack2(aB, aB);
        apn = *(const unsigned long long*)(sActCol + (k + 1) * ACT_ROW);  // row 64 = pad

        const ulonglong2* w = (const ulonglong2*)(sWT + k * 64);
        #pragma unroll
        for (int q = 0; q < 16; ++q) {
            ulonglong2 wv = w[q];                 // warp-uniform -> broadcast LDS.128
            acc0[2 * q]     = fma2(wv.x, a2A, acc0[2 * q]);
            acc0[2 * q + 1] = fma2(wv.y, a2A, acc0[2 * q + 1]);
            acc1[2 * q]     = fma2(wv.x, a2B, acc1[2 * q]);
            acc1[2 * q + 1] = fma2(wv.y, a2B, acc1[2 * q + 1]);
        }
    }

    // ReLU + repack (neuron-pair packing -> eval packing) + store (in-place safe)
    #pragma unroll
    for (int jp = 0; jp < 32; ++jp) {
        float a0, a1, b0v, b1v;
        unpack2(acc0[jp], a0, a1);
        unpack2(acc1[jp], b0v, b1v);
        a0 = fmaxf(a0, 0.f); a1 = fmaxf(a1, 0.f);
        b0v = fmaxf(b0v, 0.f); b1v = fmaxf(b1v, 0.f);
        *(unsigned long long*)(sActCol + (2 * jp) * ACT_ROW)     = pack2(a0, b0v);
        *(unsigned long long*)(sActCol + (2 * jp + 1) * ACT_ROW) = pack2(a1, b1v);
    }
}

// ---------------- templated eval body (compile-time MODE) ----------------------
template <int MODE>
__device__ __forceinline__ void eval_body(
    const float* __restrict__ W0, const float* __restrict__ b0,
    const float* __restrict__ W1, const float* __restrict__ b1,
    const float* __restrict__ W2, const float* __restrict__ b2,
    const float* __restrict__ W3, const float* __restrict__ b3,
    const float* __restrict__ Wf, const float* __restrict__ h,
    float* __restrict__ out, float* __restrict__ sm, int blk)
{
    const int tid = threadIdx.x;

    // ---- cooperative fill ----
    for (int idx = tid; idx < 4096; idx += TPB) {
        int k = idx >> 6, j = idx & 63;
        sm[OFF_W1T + idx] = W1[j * 64 + k];
        sm[OFF_W2T + idx] = W2[j * 64 + k];
    }
    if (tid < 64) {
        #pragma unroll
        for (int d = 0; d < 5; ++d) sm[OFF_W0 + tid * 8 + d] = W0[tid * 5 + d];
        sm[OFF_W0 + tid * 8 + 5] = b0[tid];
        sm[OFF_B1 + tid] = b1[tid];
        sm[OFF_B2 + tid] = b2[tid];
        float w3 = W3[tid];
        sm[OFF_W3D + 2 * tid]     = w3;
        sm[OFF_W3D + 2 * tid + 1] = w3;
    }
    if (tid < 5)   sm[OFF_WF + tid] = Wf[tid];
    if (tid == 64) sm[OFF_B3] = b3[0];

    // ---- per-eval params (2 evals per thread, compile-time NS) ----
    constexpr int NS  = (MODE == 0) ? 52 : 51;
    constexpr int TOT = BATCH * NS;
    int E0 = (blk * TPB + tid) * 2;
    const bool valid = (E0 < TOT);
    if (!valid) E0 = 0;                        // clamp; stores are guarded
    const int E1 = E0 + 1;
    const int row0 = E0 / NS, slot0 = E0 - row0 * NS;
    const int row1 = E1 / NS, slot1 = E1 - row1 * NS;

    float XA, XB;
    {
        float lo = (MODE == 0) ? 0.f : g_x2[row0];
        float hi = (MODE == 0) ? g_x[row0] : g_xfinal;
        int sc = (slot0 < S51) ? slot0 : 0;
        XA = lo + (hi - lo) * (g_ccs[sc] + 1.f) * 0.5f;
        if (MODE == 0 && slot0 == S51) XA = g_x2[row0];
    }
    {
        float lo = (MODE == 0) ? 0.f : g_x2[row1];
        float hi = (MODE == 0) ? g_x[row1] : g_xfinal;
        int sc = (slot1 < S51) ? slot1 : 0;
        XB = lo + (hi - lo) * (g_ccs[sc] + 1.f) * 0.5f;
        if (MODE == 0 && slot1 == S51) XB = g_x2[row1];
    }
    const float hA0 = h[row0 * 4 + 0], hA1 = h[row0 * 4 + 1];
    const float hA2 = h[row0 * 4 + 2], hA3 = h[row0 * 4 + 3];
    const float hB0 = h[row1 * 4 + 0], hB1 = h[row1 * 4 + 1];
    const float hB2 = h[row1 * 4 + 2], hB3 = h[row1 * 4 + 3];

    __syncthreads();

    float* actCol = sm + OFF_ACT + 2 * tid;

    // ---- layer 0: 5 -> 64 + ReLU, write packed (aA,aB) ----
    #pragma unroll 4
    for (int j = 0; j < 64; ++j) {
        const float* w = sm + OFF_W0 + j * 8;     // broadcast
        float w0 = w[0], w1 = w[1], w2 = w[2], w3v = w[3], w4 = w[4], bb = w[5];
        float aA = bb, aB = bb;
        aA = fmaf(w0, XA,  aA);  aB = fmaf(w0, XB,  aB);
        aA = fmaf(w1, hA0, aA);  aB = fmaf(w1, hB0, aB);
        aA = fmaf(w2, hA1, aA);  aB = fmaf(w2, hB1, aB);
        aA = fmaf(w3v, hA2, aA); aB = fmaf(w3v, hB2, aB);
        aA = fmaf(w4, hA3, aA);  aB = fmaf(w4, hB3, aB);
        *(unsigned long long*)(actCol + j * ACT_ROW) = pack2(fmaxf(aA, 0.f), fmaxf(aB, 0.f));
    }

    // ---- layers 1,2 ----
    layer64x2(sm + OFF_W1T, sm + OFF_B1, actCol);
    layer64x2(sm + OFF_W2T, sm + OFF_B2, actCol);

    // ---- layer 3: 64 -> 1 for both evals (packed) ----
    unsigned long long yacc = pack2(sm[OFF_B3], sm[OFF_B3]);
    #pragma unroll 8
    for (int k = 0; k < 64; ++k) {
        unsigned long long ap = *(const unsigned long long*)(actCol + k * ACT_ROW);
        unsigned long long wd = *(const unsigned long long*)(sm + OFF_W3D + 2 * k);
        yacc = fma2(wd, ap, yacc);
    }
    float yA, yB;
    unpack2(yacc, yA, yB);

    // ---- epilogue per eval ----
    constexpr float P0 = (MODE == 0) ? 1.1f : 1.5f;
    constexpr float P1 = (MODE == 0) ? 1.1f : 2.0f;
    constexpr float P2 = (MODE == 0) ? 1.5f : 2.5f;
    constexpr float P3 = (MODE == 0) ? 2.0f : 3.0f;
    constexpr float P4 = (MODE == 0) ? 2.5f : 3.5f;
    const float wf0 = sm[OFF_WF + 0], wf1 = sm[OFF_WF + 1], wf2 = sm[OFF_WF + 2];
    const float wf3 = sm[OFF_WF + 3], wf4 = sm[OFF_WF + 4];

    #pragma unroll
    for (int e = 0; e < 2; ++e) {
        float y    = e ? yB : yA;
        int   row  = e ? row1 : row0;
        int   slot = e ? slot1 : slot0;
        float z  = (y > 0.f) ? (y + 1.f) : __expf(y);
        float lg = __log2f(z);
        float g = 0.f;
        g += __fdividef(wf0, exp2f(P0 * lg) + 1.f);
        g += __fdividef(wf1, exp2f(P1 * lg) + 1.f);
        g += __fdividef(wf2, exp2f(P2 * lg) + 1.f);
        g += __fdividef(wf3, exp2f(P3 * lg) + 1.f);
        g += __fdividef(wf4, exp2f(P4 * lg) + 1.f);
        float val = fmaxf(g, 0.f);

        if (valid) {
            if (MODE == 0 && slot == S51) out[BATCH + row] = val;      // out_first
            else g_vals[MODE][row * 52 + slot] = g_ccw[slot] * val;
        }
    }
}

// ---------------- merged eval kernel --------------------------------------------
__global__ void __launch_bounds__(TPB, 1) k_eval(
    const float* __restrict__ f1W0, const float* __restrict__ f1b0,
    const float* __restrict__ f1W1, const float* __restrict__ f1b1,
    const float* __restrict__ f1W2, const float* __restrict__ f1b2,
    const float* __restrict__ f1W3, const float* __restrict__ f1b3,
    const float* __restrict__ f1Wf,
    const float* __restrict__ f2W0, const float* __restrict__ f2b0,
    const float* __restrict__ f2W1, const float* __restrict__ f2b1,
    const float* __restrict__ f2W2, const float* __restrict__ f2b2,
    const float* __restrict__ f2W3, const float* __restrict__ f2b3,
    const float* __restrict__ f2Wf,
    const float* __restrict__ h, float* __restrict__ out)
{
    extern __shared__ float sm[];
    if (blockIdx.x < NBLK0)
        eval_body<0>(f1W0, f1b0, f1W1, f1b1, f1W2, f1b2, f1W3, f1b3, f1Wf,
                     h, out, sm, blockIdx.x);
    else
        eval_body<1>(f2W0, f2b0, f2W1, f2b1, f2W2, f2b2, f2W3, f2b3, f2Wf,
                     h, out, sm, blockIdx.x - NBLK0);
}

// ---------------- merged deterministic quadrature reduce -----------------------
__global__ void k_reduce(float* __restrict__ out) {
    const bool m0 = (blockIdx.x < BATCH / 8);
    int blk  = m0 ? blockIdx.x : blockIdx.x - BATCH / 8;
    int row  = blk * 8 + (threadIdx.x >> 5);
    int lane = threadIdx.x & 31;
    const float* v = (m0 ? g_vals[0] : g_vals[1]) + row * 52;
    float s = v[lane];
    if (lane < 19) s += v[32 + lane];
    #pragma unroll
    for (int off = 16; off; off >>= 1) s += __shfl_xor_sync(0xffffffffu, s, off);
    if (lane == 0) {
        if (m0) out[row]             = s * g_x[row] * 0.5f;
        else    out[2 * BATCH + row] = s * (g_xfinal - g_x2[row]) * 0.5f * ALPHA_INV;
    }
}

// ---------------- launch ---------------------------------------------------------
extern "C" void kernel_launch(void* const* d_in, const int* in_sizes, int n_in,
                              void* d_out, int out_size) {
    (void)in_sizes; (void)n_in; (void)out_size;
    const float* x_ = (const float*)d_in[0];
    const float* h_ = (const float*)d_in[1];
    const float* lw = (const float*)d_in[2];
    const float* sp = (const float*)d_in[3];
    float* out = (float*)d_out;

    cudaFuncSetAttribute(k_eval, cudaFuncAttributeMaxDynamicSharedMemorySize, SMEM_BYTES);

    k_init_cc<<<1, 64>>>();
    k_xm<<<BATCH / 8, 256>>>(x_, lw);

    for (int step = 0; step < 2; ++step) {
        k_prep<<<1, 1024>>>(sp, out, step);
        k_eval<<<NBLK0 + NBLK1, TPB, SMEM_BYTES>>>(
            (const float*)d_in[4],  (const float*)d_in[5],  (const float*)d_in[6],
            (const float*)d_in[7],  (const float*)d_in[8],  (const float*)d_in[9],
            (const float*)d_in[10], (const float*)d_in[11], (const float*)d_in[12],
            (const float*)d_in[13], (const float*)d_in[14], (const float*)d_in[15],
            (const float*)d_in[16], (const float*)d_in[17], (const float*)d_in[18],
            (const float*)d_in[19], (const float*)d_in[20], (const float*)d_in[21],
            h_, out);
        k_reduce<<<2 * (BATCH / 8), 256>>>(out);
    }
}

// round 12
// speedup vs baseline: 1.0087x; 1.0087x over previous
#include <cuda_runtime.h>
#include <math_constants.h>

#define NB 50
#define S51 51
#define BATCH 4096
#define NFEAT 100
#define ALPHA_INV (1.0f/0.9f)

// ---------------- device globals (scratch) ----------------------------------
__device__ float g_xm[BATCH];
__device__ float g_x[BATCH];
__device__ float g_x2[BATCH];
__device__ float g_xfinal;
__device__ float g_ccw[S51];
__device__ float g_ccs[S51];
__device__ float g_vals[2][BATCH * 52];

// ---------------- packed f32x2 helpers --------------------------------------
__device__ __forceinline__ unsigned long long fma2(unsigned long long a,
                                                   unsigned long long b,
                                                   unsigned long long c) {
    unsigned long long d;
    asm("fma.rn.f32x2 %0, %1, %2, %3;" : "=l"(d) : "l"(a), "l"(b), "l"(c));
    return d;
}
__device__ __forceinline__ unsigned long long pack2(float lo, float hi) {
    unsigned long long d;
    asm("mov.b64 %0, {%1, %2};" : "=l"(d) : "f"(lo), "f"(hi));
    return d;
}
__device__ __forceinline__ void unpack2(unsigned long long v, float& lo, float& hi) {
    asm("mov.b64 {%0, %1}, %2;" : "=f"(lo), "=f"(hi) : "l"(v));
}

// ---------------- SMEM layout (floats): weights only, ~38KB -------------------
#define OFF_W1T  0            // transposed W1: [k][j], 4096
#define OFF_W2T  4096         // transposed W2
#define OFF_W0   8192         // [64][8]: 5 weights + bias (+2 pad)
#define OFF_B1   8704
#define OFF_B2   8768
#define OFF_W3   8832         // 64
#define OFF_WF   8896         // 5
#define OFF_B3   8901
#define SMEM_FLOATS 8904
#define SMEM_BYTES (SMEM_FLOATS * 4)

// ---------------- CC weights (fp64, parallel: 51 blocks x 64 thr) ------------
__global__ void k_init_cc() {
    __shared__ double sred[64];
    int j = blockIdx.x;
    int i = threadIdx.x;
    double t = 0.0;
    if (i <= NB) {
        double w;
        if (i & 1)        w = 0.0;
        else if (i == 0)  w = 1.0;
        else              w = 2.0 / (1.0 - (double)i * (double)i);
        double l;
        if (j == 0) l = 0.5;
        else {
            l = cos((double)i * (double)j * CUDART_PI / (double)NB);
            if (j == NB) l *= 0.5;
        }
        t = l * (2.0 / (double)NB) * w;
    }
    sred[i] = t;
    __syncthreads();
    for (int off = 32; off; off >>= 1) {
        if (i < off) sred[i] += sred[i + off];
        __syncthreads();
    }
    if (i == 0) {
        g_ccw[j] = (float)sred[0];
        g_ccs[j] = (float)cos((double)j * CUDART_PI / (double)NB);
    }
}

// ---------------- xm = x_ @ log_weight ----------------------------------------
__global__ void k_xm(const float* __restrict__ x_, const float* __restrict__ lw) {
    int warp = (blockIdx.x * blockDim.x + threadIdx.x) >> 5;
    int lane = threadIdx.x & 31;
    if (warp >= BATCH) return;
    const float* row = x_ + (size_t)warp * NFEAT;
    float p = 0.f;
    for (int j = lane; j < NFEAT; j += 32) p = fmaf(row[j], lw[j], p);
    #pragma unroll
    for (int off = 16; off; off >>= 1) p += __shfl_xor_sync(0xffffffffu, p, off);
    if (lane == 0) g_xm[warp] = p;
}

// ---------------- per-step prep ------------------------------------------------
__global__ void k_prep(const float* __restrict__ sp, const float* __restrict__ out, int step) {
    __shared__ float smax[1024];
    int tid = threadIdx.x;
    float lam = 1.f / (1.f + __expf(-sp[0]));
    float lmax = -CUDART_INF_F;
    for (int b = tid; b < BATCH; b += 1024) {
        float I1v = step ? out[b]             : 0.f;
        float I2v = step ? out[2 * BATCH + b] : 0.f;
        float xmv = g_xm[b];
        g_x[b]  = (1.f - lam) * xmv + lam * I1v;
        float x2v = (1.f - lam) * xmv + lam * I2v;
        g_x2[b] = x2v;
        lmax = fmaxf(lmax, x2v);
    }
    smax[tid] = lmax;
    __syncthreads();
    for (int off = 512; off; off >>= 1) {
        if (tid < off) smax[tid] = fmaxf(smax[tid], smax[tid + off]);
        __syncthreads();
    }
    if (tid == 0) g_xfinal = smax[0] + 10.f;
}

// ---------------- 64->64 layer, acts in registers -----------------------------
// aold[32]: pre-ReLU acts packed (n2jp, n2jp+1). anew gets pre-ReLU outputs.
// ReLU applied at extraction. Weight reads are warp-uniform broadcast LDS.128.
__device__ __forceinline__ void layerR(const float* __restrict__ sWT,
                                       const float* __restrict__ sbias,
                                       const unsigned long long* __restrict__ aold,
                                       unsigned long long* __restrict__ anew) {
    #pragma unroll
    for (int jp = 0; jp < 32; ++jp)
        anew[jp] = *(const unsigned long long*)(sbias + 2 * jp);

    #pragma unroll 2
    for (int k = 0; k < 64; ++k) {
        float lo, hi;
        unpack2(aold[k >> 1], lo, hi);
        float v = fmaxf((k & 1) ? hi : lo, 0.f);    // compile-time lane select
        unsigned long long a2 = pack2(v, v);
        const ulonglong2* w = (const ulonglong2*)(sWT + k * 64);
        #pragma unroll
        for (int q = 0; q < 16; ++q) {
            ulonglong2 wv = w[q];
            anew[2 * q]     = fma2(wv.x, a2, anew[2 * q]);
            anew[2 * q + 1] = fma2(wv.y, a2, anew[2 * q + 1]);
        }
    }
}

// ---------------- eval kernel: 1 eval/thread, acts never touch smem ------------
template <int MODE>
__global__ void __launch_bounds__(256, 1) k_eval(
    const float* __restrict__ W0, const float* __restrict__ b0,
    const float* __restrict__ W1, const float* __restrict__ b1,
    const float* __restrict__ W2, const float* __restrict__ b2,
    const float* __restrict__ W3, const float* __restrict__ b3,
    const float* __restrict__ Wf, const float* __restrict__ h,
    float* __restrict__ out)
{
    __shared__ float sm[SMEM_FLOATS];
    const int tid = threadIdx.x;

    // ---- cooperative fill: transposed hidden weights + small params ----
    for (int idx = tid; idx < 4096; idx += 256) {
        int k = idx >> 6, j = idx & 63;
        sm[OFF_W1T + idx] = W1[j * 64 + k];
        sm[OFF_W2T + idx] = W2[j * 64 + k];
    }
    if (tid < 64) {
        #pragma unroll
        for (int d = 0; d < 5; ++d) sm[OFF_W0 + tid * 8 + d] = W0[tid * 5 + d];
        sm[OFF_W0 + tid * 8 + 5] = b0[tid];
        sm[OFF_B1 + tid] = b1[tid];
        sm[OFF_B2 + tid] = b2[tid];
        sm[OFF_W3 + tid] = W3[tid];
    }
    if (tid < 5)   sm[OFF_WF + tid] = Wf[tid];
    if (tid == 64) sm[OFF_B3] = b3[0];

    // ---- eval params (exact grid: no tail) ----
    constexpr int NS = (MODE == 0) ? 52 : 51;
    const int E    = blockIdx.x * 256 + tid;
    const int row  = E / NS;
    const int slot = E - row * NS;

    float lo, hi;
    if (MODE == 0) { lo = 0.f;       hi = g_x[row]; }
    else           { lo = g_x2[row]; hi = g_xfinal; }
    const int sc = (slot < S51) ? slot : 0;
    float X = lo + (hi - lo) * (g_ccs[sc] + 1.f) * 0.5f;
    if (MODE == 0 && slot == S51) X = g_x2[row];

    const float h0 = h[row * 4 + 0], h1 = h[row * 4 + 1];
    const float h2 = h[row * 4 + 2], h3 = h[row * 4 + 3];
    const float ccwv = g_ccw[sc];

    __syncthreads();

    // ---- layer 0: 5 -> 64 (pre-ReLU, packed pairs in regs) ----
    unsigned long long a[32], b[32];
    #pragma unroll 4
    for (int jp = 0; jp < 32; ++jp) {
        const float* w0p = sm + OFF_W0 + (2 * jp) * 8;
        const float* w1p = sm + OFF_W0 + (2 * jp + 1) * 8;
        float vA = w0p[5], vB = w1p[5];
        vA = fmaf(w0p[0], X,  vA);  vB = fmaf(w1p[0], X,  vB);
        vA = fmaf(w0p[1], h0, vA);  vB = fmaf(w1p[1], h0, vB);
        vA = fmaf(w0p[2], h1, vA);  vB = fmaf(w1p[2], h1, vB);
        vA = fmaf(w0p[3], h2, vA);  vB = fmaf(w1p[3], h2, vB);
        vA = fmaf(w0p[4], h3, vA);  vB = fmaf(w1p[4], h3, vB);
        a[jp] = pack2(vA, vB);
    }

    // ---- layers 1,2 (register-resident acts) ----
    layerR(sm + OFF_W1T, sm + OFF_B1, a, b);
    layerR(sm + OFF_W2T, sm + OFF_B2, b, a);

    // ---- layer 3: 64 -> 1, ReLU at extraction ----
    float y = sm[OFF_B3];
    #pragma unroll
    for (int jp = 0; jp < 32; ++jp) {
        float v0, v1;
        unpack2(a[jp], v0, v1);
        y = fmaf(sm[OFF_W3 + 2 * jp],     fmaxf(v0, 0.f), y);
        y = fmaf(sm[OFF_W3 + 2 * jp + 1], fmaxf(v1, 0.f), y);
    }

    // ---- epilogue ----
    constexpr float P0 = (MODE == 0) ? 1.1f : 1.5f;
    constexpr float P1 = (MODE == 0) ? 1.1f : 2.0f;
    constexpr float P2 = (MODE == 0) ? 1.5f : 2.5f;
    constexpr float P3 = (MODE == 0) ? 2.0f : 3.0f;
    constexpr float P4 = (MODE == 0) ? 2.5f : 3.5f;

    float z  = (y > 0.f) ? (y + 1.f) : __expf(y);
    float lg = __log2f(z);
    float g = 0.f;
    g += __fdividef(sm[OFF_WF + 0], exp2f(P0 * lg) + 1.f);
    g += __fdividef(sm[OFF_WF + 1], exp2f(P1 * lg) + 1.f);
    g += __fdividef(sm[OFF_WF + 2], exp2f(P2 * lg) + 1.f);
    g += __fdividef(sm[OFF_WF + 3], exp2f(P3 * lg) + 1.f);
    g += __fdividef(sm[OFF_WF + 4], exp2f(P4 * lg) + 1.f);
    float val = fmaxf(g, 0.f);

    if (MODE == 0 && slot == S51) out[BATCH + row] = val;        // out_first
    else                          g_vals[MODE][row * 52 + slot] = ccwv * val;
}

// ---------------- merged deterministic quadrature reduce -----------------------
__global__ void k_reduce(float* __restrict__ out) {
    const bool m0 = (blockIdx.x < BATCH / 8);
    int blk  = m0 ? blockIdx.x : blockIdx.x - BATCH / 8;
    int row  = blk * 8 + (threadIdx.x >> 5);
    int lane = threadIdx.x & 31;
    const float* v = (m0 ? g_vals[0] : g_vals[1]) + row * 52;
    float s = v[lane];
    if (lane < 19) s += v[32 + lane];
    #pragma unroll
    for (int off = 16; off; off >>= 1) s += __shfl_xor_sync(0xffffffffu, s, off);
    if (lane == 0) {
        if (m0) out[row]             = s * g_x[row] * 0.5f;
        else    out[2 * BATCH + row] = s * (g_xfinal - g_x2[row]) * 0.5f * ALPHA_INV;
    }
}

// ---------------- launch ---------------------------------------------------------
extern "C" void kernel_launch(void* const* d_in, const int* in_sizes, int n_in,
                              void* d_out, int out_size) {
    (void)in_sizes; (void)n_in; (void)out_size;
    const float* x_ = (const float*)d_in[0];
    const float* h_ = (const float*)d_in[1];
    const float* lw = (const float*)d_in[2];
    const float* sp = (const float*)d_in[3];
    const float* f1p[9] = { (const float*)d_in[4],  (const float*)d_in[5],
                            (const float*)d_in[6],  (const float*)d_in[7],
                            (const float*)d_in[8],  (const float*)d_in[9],
                            (const float*)d_in[10], (const float*)d_in[11],
                            (const float*)d_in[12] };
    const float* f2p[9] = { (const float*)d_in[13], (const float*)d_in[14],
                            (const float*)d_in[15], (const float*)d_in[16],
                            (const float*)d_in[17], (const float*)d_in[18],
                            (const float*)d_in[19], (const float*)d_in[20],
                            (const float*)d_in[21] };
    float* out = (float*)d_out;

    k_init_cc<<<S51, 64>>>();
    k_xm<<<BATCH / 8, 256>>>(x_, lw);

    for (int step = 0; step < 2; ++step) {
        k_prep<<<1, 1024>>>(sp, out, step);
        // MODE 0: 4096*52 = 212992 = 832 * 256 (exact)
        k_eval<0><<<832, 256>>>(f1p[0], f1p[1], f1p[2], f1p[3], f1p[4],
                                f1p[5], f1p[6], f1p[7], f1p[8], h_, out);
        // MODE 1: 4096*51 = 208896 = 816 * 256 (exact)
        k_eval<1><<<816, 256>>>(f2p[0], f2p[1], f2p[2], f2p[3], f2p[4],
                                f2p[5], f2p[6], f2p[7], f2p[8], h_, out);
        k_reduce<<<2 * (BATCH / 8), 256>>>(out);
    }
}

// round 14
// speedup vs baseline: 1.5401x; 1.5268x over previous
#include <cuda_runtime.h>
#include <math_constants.h>

#define NB 50
#define S51 51
#define BATCH 4096
#define NFEAT 100
#define ALPHA_INV (1.0f/0.9f)

#define TPB  384             // 12 warps: warps 0-5 = neuron half 0, 6-11 = half 1
#define COLS 192             // eval-pair columns per block (384 evals)

// ---------------- device globals (scratch) ----------------------------------
__device__ float g_xm[BATCH];
__device__ float g_x[BATCH];
__device__ float g_x2[BATCH];
__device__ float g_xfinal;
__device__ float g_ccw[S51];
__device__ float g_ccs[S51];
__device__ float g_vals[2][BATCH * 52];

// ---------------- packed f32x2 helpers --------------------------------------
__device__ __forceinline__ unsigned long long fma2(unsigned long long a,
                                                   unsigned long long b,
                                                   unsigned long long c) {
    unsigned long long d;
    asm("fma.rn.f32x2 %0, %1, %2, %3;" : "=l"(d) : "l"(a), "l"(b), "l"(c));
    return d;
}
__device__ __forceinline__ unsigned long long pack2(float lo, float hi) {
    unsigned long long d;
    asm("mov.b64 %0, {%1, %2};" : "=l"(d) : "f"(lo), "f"(hi));
    return d;
}
__device__ __forceinline__ void unpack2(unsigned long long v, float& lo, float& hi) {
    asm("mov.b64 {%0, %1}, %2;" : "=f"(lo), "=f"(hi) : "l"(v));
}

// ---------------- SMEM layout (floats) ----------------------------------------
// Act buffer: [65 rows][192 cols] packed (aA,aB) u64; row 64 = prefetch pad.
#define ACT_ROW 384
#define OFF_ACT   0            // 65*384 = 24960
#define OFF_W1T   24960        // transposed W1 [k][j]
#define OFF_W2T   29056
#define OFF_W0    33152        // [64][8]
#define OFF_B1    33664
#define OFF_B2    33728
#define OFF_W3D   33792        // dup pairs (w3,w3): 128
#define OFF_WF    33920        // 5
#define OFF_B3    33925
#define OFF_PART  33928        // layer-3 partials: 2*192 u64 = 768 floats
#define SMEM_FLOATS 34696
#define SMEM_BYTES (SMEM_FLOATS * 4)

// ---------------- CC weights (fp64, parallel) ---------------------------------
__global__ void k_init_cc() {
    __shared__ double sred[64];
    int j = blockIdx.x, i = threadIdx.x;
    double t = 0.0;
    if (i <= NB) {
        double w;
        if (i & 1)        w = 0.0;
        else if (i == 0)  w = 1.0;
        else              w = 2.0 / (1.0 - (double)i * (double)i);
        double l;
        if (j == 0) l = 0.5;
        else {
            l = cos((double)i * (double)j * CUDART_PI / (double)NB);
            if (j == NB) l *= 0.5;
        }
        t = l * (2.0 / (double)NB) * w;
    }
    sred[i] = t;
    __syncthreads();
    for (int off = 32; off; off >>= 1) {
        if (i < off) sred[i] += sred[i + off];
        __syncthreads();
    }
    if (i == 0) {
        g_ccw[j] = (float)sred[0];
        g_ccs[j] = (float)cos((double)j * CUDART_PI / (double)NB);
    }
}

// ---------------- xm = x_ @ log_weight ----------------------------------------
__global__ void k_xm(const float* __restrict__ x_, const float* __restrict__ lw) {
    int warp = (blockIdx.x * blockDim.x + threadIdx.x) >> 5;
    int lane = threadIdx.x & 31;
    if (warp >= BATCH) return;
    const float* row = x_ + (size_t)warp * NFEAT;
    float p = 0.f;
    for (int j = lane; j < NFEAT; j += 32) p = fmaf(row[j], lw[j], p);
    #pragma unroll
    for (int off = 16; off; off >>= 1) p += __shfl_xor_sync(0xffffffffu, p, off);
    if (lane == 0) g_xm[warp] = p;
}

// ---------------- per-step prep ------------------------------------------------
__global__ void k_prep(const float* __restrict__ sp, const float* __restrict__ out, int step) {
    __shared__ float smax[1024];
    int tid = threadIdx.x;
    float lam = 1.f / (1.f + __expf(-sp[0]));
    float lmax = -CUDART_INF_F;
    for (int b = tid; b < BATCH; b += 1024) {
        float I1v = step ? out[b]             : 0.f;
        float I2v = step ? out[2 * BATCH + b] : 0.f;
        float xmv = g_xm[b];
        g_x[b]  = (1.f - lam) * xmv + lam * I1v;
        float x2v = (1.f - lam) * xmv + lam * I2v;
        g_x2[b] = x2v;
        lmax = fmaxf(lmax, x2v);
    }
    smax[tid] = lmax;
    __syncthreads();
    for (int off = 512; off; off >>= 1) {
        if (tid < off) smax[tid] = fmaxf(smax[tid], smax[tid + off]);
        __syncthreads();
    }
    if (tid == 0) g_xfinal = smax[0] + 10.f;
}

// ---------------- 64->64 half-layer: thread = 2 evals x 32 neurons -------------
// Warp-uniform half offset -> weight LDS.128 stays broadcast (8 per k).
// Reads all 64 act rows of own column; writes own 32 rows. Caller syncs.
__device__ __forceinline__ void layer_half(const float* __restrict__ sWT,
                                           const float* __restrict__ sbias,
                                           float* __restrict__ actCol, int half,
                                           unsigned long long* acc0,
                                           unsigned long long* acc1) {
    const float* bb = sbias + half * 32;
    #pragma unroll
    for (int jp = 0; jp < 16; ++jp) {
        unsigned long long bp = *(const unsigned long long*)(bb + 2 * jp);
        acc0[jp] = bp;
        acc1[jp] = bp;
    }

    unsigned long long apn = *(const unsigned long long*)(actCol);   // k=0

    #pragma unroll 2
    for (int k = 0; k < 64; ++k) {
        float aA, aB;
        unpack2(apn, aA, aB);
        unsigned long long a2A = pack2(aA, aA);
        unsigned long long a2B = pack2(aB, aB);
        apn = *(const unsigned long long*)(actCol + (k + 1) * ACT_ROW);  // row 64 = pad

        const ulonglong2* w = (const ulonglong2*)(sWT + k * 64 + half * 32);
        #pragma unroll
        for (int q = 0; q < 8; ++q) {
            ulonglong2 wv = w[q];                 // warp-uniform broadcast
            acc0[2 * q]     = fma2(wv.x, a2A, acc0[2 * q]);
            acc0[2 * q + 1] = fma2(wv.y, a2A, acc0[2 * q + 1]);
            acc1[2 * q]     = fma2(wv.x, a2B, acc1[2 * q]);
            acc1[2 * q + 1] = fma2(wv.y, a2B, acc1[2 * q + 1]);
        }
    }
}

__device__ __forceinline__ void store_half(float* __restrict__ actCol, int half,
                                           const unsigned long long* acc0,
                                           const unsigned long long* acc1) {
    float* base = actCol + (half * 32) * ACT_ROW;
    #pragma unroll
    for (int jp = 0; jp < 16; ++jp) {
        float a0, a1, b0v, b1v;
        unpack2(acc0[jp], a0, a1);   // eval A, local neurons 2jp, 2jp+1
        unpack2(acc1[jp], b0v, b1v); // eval B
        a0 = fmaxf(a0, 0.f); a1 = fmaxf(a1, 0.f);
        b0v = fmaxf(b0v, 0.f); b1v = fmaxf(b1v, 0.f);
        *(unsigned long long*)(base + (2 * jp) * ACT_ROW)     = pack2(a0, b0v);
        *(unsigned long long*)(base + (2 * jp + 1) * ACT_ROW) = pack2(a1, b1v);
    }
}

// ---------------- eval kernel ----------------------------------------------------
template <int MODE>
__global__ void __launch_bounds__(TPB, 1) k_eval(
    const float* __restrict__ W0, const float* __restrict__ b0,
    const float* __restrict__ W1, const float* __restrict__ b1,
    const float* __restrict__ W2, const float* __restrict__ b2,
    const float* __restrict__ W3, const float* __restrict__ b3,
    const float* __restrict__ Wf, const float* __restrict__ h,
    float* __restrict__ out)
{
    extern __shared__ float sm[];
    const int tid  = threadIdx.x;
    const int half = (tid >= COLS) ? 1 : 0;     // warp-uniform (COLS = 6 warps)
    const int q    = tid - half * COLS;         // eval-pair column

    // ---- cooperative fill ----
    for (int idx = tid; idx < 4096; idx += TPB) {
        int k = idx >> 6, j = idx & 63;
        sm[OFF_W1T + idx] = W1[j * 64 + k];
        sm[OFF_W2T + idx] = W2[j * 64 + k];
    }
    if (tid < 64) {
        #pragma unroll
        for (int d = 0; d < 5; ++d) sm[OFF_W0 + tid * 8 + d] = W0[tid * 5 + d];
        sm[OFF_W0 + tid * 8 + 5] = b0[tid];
        sm[OFF_B1 + tid] = b1[tid];
        sm[OFF_B2 + tid] = b2[tid];
        float w3 = W3[tid];
        sm[OFF_W3D + 2 * tid]     = w3;
        sm[OFF_W3D + 2 * tid + 1] = w3;
    }
    if (tid < 5)   sm[OFF_WF + tid] = Wf[tid];
    if (tid == 64) sm[OFF_B3] = b3[0];

    // ---- per-eval params ----
    constexpr int NS  = (MODE == 0) ? 52 : 51;
    constexpr int TOT = BATCH * NS;
    int E0 = (blockIdx.x * COLS + q) * 2;
    const bool valid = (E0 < TOT);
    if (!valid) E0 = 0;
    const int E1 = E0 + 1;
    const int row0 = E0 / NS, slot0 = E0 - row0 * NS;
    const int row1 = E1 / NS, slot1 = E1 - row1 * NS;

    float XA, XB;
    {
        float lo = (MODE == 0) ? 0.f : g_x2[row0];
        float hi = (MODE == 0) ? g_x[row0] : g_xfinal;
        int sc = (slot0 < S51) ? slot0 : 0;
        XA = lo + (hi - lo) * (g_ccs[sc] + 1.f) * 0.5f;
        if (MODE == 0 && slot0 == S51) XA = g_x2[row0];
    }
    {
        float lo = (MODE == 0) ? 0.f : g_x2[row1];
        float hi = (MODE == 0) ? g_x[row1] : g_xfinal;
        int sc = (slot1 < S51) ? slot1 : 0;
        XB = lo + (hi - lo) * (g_ccs[sc] + 1.f) * 0.5f;
        if (MODE == 0 && slot1 == S51) XB = g_x2[row1];
    }
    const float hA0 = h[row0 * 4 + 0], hA1 = h[row0 * 4 + 1];
    const float hA2 = h[row0 * 4 + 2], hA3 = h[row0 * 4 + 3];
    const float hB0 = h[row1 * 4 + 0], hB1 = h[row1 * 4 + 1];
    const float hB2 = h[row1 * 4 + 2], hB3 = h[row1 * 4 + 3];

    __syncthreads();

    float* actCol = sm + OFF_ACT + 2 * q;

    // ---- layer 0: own 32 neurons for own 2 evals ----
    #pragma unroll 4
    for (int jp = 0; jp < 16; ++jp) {
        const float* w0p = sm + OFF_W0 + (half * 32 + 2 * jp) * 8;
        const float* w1p = w0p + 8;
        float vA0 = w0p[5], vB0 = w0p[5], vA1 = w1p[5], vB1 = w1p[5];
        vA0 = fmaf(w0p[0], XA,  vA0);  vB0 = fmaf(w0p[0], XB,  vB0);
        vA1 = fmaf(w1p[0], XA,  vA1);  vB1 = fmaf(w1p[0], XB,  vB1);
        vA0 = fmaf(w0p[1], hA0, vA0);  vB0 = fmaf(w0p[1], hB0, vB0);
        vA1 = fmaf(w1p[1], hA0, vA1);  vB1 = fmaf(w1p[1], hB0, vB1);
        vA0 = fmaf(w0p[2], hA1, vA0);  vB0 = fmaf(w0p[2], hB1, vB0);
        vA1 = fmaf(w1p[2], hA1, vA1);  vB1 = fmaf(w1p[2], hB1, vB1);
        vA0 = fmaf(w0p[3], hA2, vA0);  vB0 = fmaf(w0p[3], hB2, vB0);
        vA1 = fmaf(w1p[3], hA2, vA1);  vB1 = fmaf(w1p[3], hB2, vB1);
        vA0 = fmaf(w0p[4], hA3, vA0);  vB0 = fmaf(w0p[4], hB3, vB0);
        vA1 = fmaf(w1p[4], hA3, vA1);  vB1 = fmaf(w1p[4], hB3, vB1);
        float* base = actCol + (half * 32) * ACT_ROW;
        *(unsigned long long*)(base + (2 * jp) * ACT_ROW)
            = pack2(fmaxf(vA0, 0.f), fmaxf(vB0, 0.f));
        *(unsigned long long*)(base + (2 * jp + 1) * ACT_ROW)
            = pack2(fmaxf(vA1, 0.f), fmaxf(vB1, 0.f));
    }
    __syncthreads();

    unsigned long long acc0[16], acc1[16];

    // ---- layer 1 ----
    layer_half(sm + OFF_W1T, sm + OFF_B1, actCol, half, acc0, acc1);
    __syncthreads();                            // all reads done before overwrite
    store_half(actCol, half, acc0, acc1);
    __syncthreads();

    // ---- layer 2 ----
    layer_half(sm + OFF_W2T, sm + OFF_B2, actCol, half, acc0, acc1);
    __syncthreads();
    store_half(actCol, half, acc0, acc1);
    __syncthreads();

    // ---- layer 3: partial dot over own 32 rows ----
    unsigned long long yacc = (half == 0) ? pack2(sm[OFF_B3], sm[OFF_B3])
                                          : 0ull;
    {
        const float* base = actCol + (half * 32) * ACT_ROW;
        #pragma unroll 8
        for (int kk = 0; kk < 32; ++kk) {
            unsigned long long ap = *(const unsigned long long*)(base + kk * ACT_ROW);
            unsigned long long wd = *(const unsigned long long*)(sm + OFF_W3D + 2 * (half * 32 + kk));
            yacc = fma2(wd, ap, yacc);
        }
    }
    *(unsigned long long*)(sm + OFF_PART + (half * COLS + q) * 2) = yacc;
    __syncthreads();

    if (half == 0) {
        float yA, yB, zA, zB;
        unpack2(yacc, yA, yB);
        unsigned long long other = *(const unsigned long long*)(sm + OFF_PART + (COLS + q) * 2);
        unpack2(other, zA, zB);
        yA += zA;
        yB += zB;

        constexpr float P0 = (MODE == 0) ? 1.1f : 1.5f;
        constexpr float P1 = (MODE == 0) ? 1.1f : 2.0f;
        constexpr float P2 = (MODE == 0) ? 1.5f : 2.5f;
        constexpr float P3 = (MODE == 0) ? 2.0f : 3.0f;
        constexpr float P4 = (MODE == 0) ? 2.5f : 3.5f;
        const float wf0 = sm[OFF_WF + 0], wf1 = sm[OFF_WF + 1], wf2 = sm[OFF_WF + 2];
        const float wf3 = sm[OFF_WF + 3], wf4 = sm[OFF_WF + 4];

        #pragma unroll
        for (int e = 0; e < 2; ++e) {
            float y    = e ? yB : yA;
            int   row  = e ? row1 : row0;
            int   slot = e ? slot1 : slot0;
            float z  = (y > 0.f) ? (y + 1.f) : __expf(y);
            float lg = __log2f(z);
            float g = 0.f;
            g += __fdividef(wf0, exp2f(P0 * lg) + 1.f);
            g += __fdividef(wf1, exp2f(P1 * lg) + 1.f);
            g += __fdividef(wf2, exp2f(P2 * lg) + 1.f);
            g += __fdividef(wf3, exp2f(P3 * lg) + 1.f);
            g += __fdividef(wf4, exp2f(P4 * lg) + 1.f);
            float val = fmaxf(g, 0.f);

            if (valid) {
                if (MODE == 0 && slot == S51) out[BATCH + row] = val;    // out_first
                else g_vals[MODE][row * 52 + slot] = g_ccw[slot] * val;
            }
        }
    }
}

// ---------------- merged deterministic quadrature reduce -----------------------
__global__ void k_reduce(float* __restrict__ out) {
    const bool m0 = (blockIdx.x < BATCH / 8);
    int blk  = m0 ? blockIdx.x : blockIdx.x - BATCH / 8;
    int row  = blk * 8 + (threadIdx.x >> 5);
    int lane = threadIdx.x & 31;
    const float* v = (m0 ? g_vals[0] : g_vals[1]) + row * 52;
    float s = v[lane];
    if (lane < 19) s += v[32 + lane];
    #pragma unroll
    for (int off = 16; off; off >>= 1) s += __shfl_xor_sync(0xffffffffu, s, off);
    if (lane == 0) {
        if (m0) out[row]             = s * g_x[row] * 0.5f;
        else    out[2 * BATCH + row] = s * (g_xfinal - g_x2[row]) * 0.5f * ALPHA_INV;
    }
}

// ---------------- launch ---------------------------------------------------------
extern "C" void kernel_launch(void* const* d_in, const int* in_sizes, int n_in,
                              void* d_out, int out_size) {
    (void)in_sizes; (void)n_in; (void)out_size;
    const float* x_ = (const float*)d_in[0];
    const float* h_ = (const float*)d_in[1];
    const float* lw = (const float*)d_in[2];
    const float* sp = (const float*)d_in[3];
    const float* f1p[9] = { (const float*)d_in[4],  (const float*)d_in[5],
                            (const float*)d_in[6],  (const float*)d_in[7],
                            (const float*)d_in[8],  (const float*)d_in[9],
                            (const float*)d_in[10], (const float*)d_in[11],
                            (const float*)d_in[12] };
    const float* f2p[9] = { (const float*)d_in[13], (const float*)d_in[14],
                            (const float*)d_in[15], (const float*)d_in[16],
                            (const float*)d_in[17], (const float*)d_in[18],
                            (const float*)d_in[19], (const float*)d_in[20],
                            (const float*)d_in[21] };
    float* out = (float*)d_out;

    cudaFuncSetAttribute(k_eval<0>, cudaFuncAttributeMaxDynamicSharedMemorySize, SMEM_BYTES);
    cudaFuncSetAttribute(k_eval<1>, cudaFuncAttributeMaxDynamicSharedMemorySize, SMEM_BYTES);

    k_init_cc<<<S51, 64>>>();
    k_xm<<<BATCH / 8, 256>>>(x_, lw);

    for (int step = 0; step < 2; ++step) {
        k_prep<<<1, 1024>>>(sp, out, step);
        // MODE 0: 212992 evals / 384 per block -> 555 blocks (tail guarded)
        k_eval<0><<<555, TPB, SMEM_BYTES>>>(f1p[0], f1p[1], f1p[2], f1p[3], f1p[4],
                                            f1p[5], f1p[6], f1p[7], f1p[8], h_, out);
        // MODE 1: 208896 evals / 384 per block -> 544 blocks (exact)
        k_eval<1><<<544, TPB, SMEM_BYTES>>>(f2p[0], f2p[1], f2p[2], f2p[3], f2p[4],
                                            f2p[5], f2p[6], f2p[7], f2p[8], h_, out);
        k_reduce<<<2 * (BATCH / 8), 256>>>(out);
    }
}

// round 15
// speedup vs baseline: 1.6287x; 1.0575x over previous
#include <cuda_runtime.h>
#include <math_constants.h>

#define NB 50
#define S51 51
#define BATCH 4096
#define NFEAT 100
#define ALPHA_INV (1.0f/0.9f)

#define TPB  384             // 12 warps = 4 quarters x 3 warps (96 threads)
#define QCOL 96              // eval columns per block; 4 evals each -> 384 evals

// ---------------- device globals (scratch) ----------------------------------
__device__ float g_xm[BATCH];
__device__ float g_x[BATCH];
__device__ float g_x2[BATCH];
__device__ float g_xfinal;
__device__ float g_ccw[S51];
__device__ float g_ccs[S51];
__device__ float g_vals[2][BATCH * 52];

// ---------------- packed f32x2 helpers --------------------------------------
__device__ __forceinline__ unsigned long long fma2(unsigned long long a,
                                                   unsigned long long b,
                                                   unsigned long long c) {
    unsigned long long d;
    asm("fma.rn.f32x2 %0, %1, %2, %3;" : "=l"(d) : "l"(a), "l"(b), "l"(c));
    return d;
}
__device__ __forceinline__ unsigned long long pack2(float lo, float hi) {
    unsigned long long d;
    asm("mov.b64 %0, {%1, %2};" : "=l"(d) : "f"(lo), "f"(hi));
    return d;
}
__device__ __forceinline__ void unpack2(unsigned long long v, float& lo, float& hi) {
    asm("mov.b64 {%0, %1}, %2;" : "=f"(lo), "=f"(hi) : "l"(v));
}

// ---------------- SMEM layout (floats) ----------------------------------------
// Act buffer: [65 rows][96 cols x 4 evals] floats; row 64 = prefetch pad.
#define ACT_ROW 384
#define OFF_ACT   0            // 65*384 = 24960
#define OFF_W1T   24960        // transposed W1 [k][j]
#define OFF_W2T   29056
#define OFF_W0    33152        // [64][8]
#define OFF_B1    33664
#define OFF_B2    33728
#define OFF_W3    33792        // 64
#define OFF_WF    33856        // 5
#define OFF_B3    33861
#define OFF_PART  33864        // layer-3 partials: 4 quarters x 96 cols x 4 = 1536
#define SMEM_FLOATS 35400
#define SMEM_BYTES (SMEM_FLOATS * 4)

// ---------------- CC weights (fp64, parallel) ---------------------------------
__global__ void k_init_cc() {
    __shared__ double sred[64];
    int j = blockIdx.x, i = threadIdx.x;
    double t = 0.0;
    if (i <= NB) {
        double w;
        if (i & 1)        w = 0.0;
        else if (i == 0)  w = 1.0;
        else              w = 2.0 / (1.0 - (double)i * (double)i);
        double l;
        if (j == 0) l = 0.5;
        else {
            l = cos((double)i * (double)j * CUDART_PI / (double)NB);
            if (j == NB) l *= 0.5;
        }
        t = l * (2.0 / (double)NB) * w;
    }
    sred[i] = t;
    __syncthreads();
    for (int off = 32; off; off >>= 1) {
        if (i < off) sred[i] += sred[i + off];
        __syncthreads();
    }
    if (i == 0) {
        g_ccw[j] = (float)sred[0];
        g_ccs[j] = (float)cos((double)j * CUDART_PI / (double)NB);
    }
}

// ---------------- xm = x_ @ log_weight ----------------------------------------
__global__ void k_xm(const float* __restrict__ x_, const float* __restrict__ lw) {
    int warp = (blockIdx.x * blockDim.x + threadIdx.x) >> 5;
    int lane = threadIdx.x & 31;
    if (warp >= BATCH) return;
    const float* row = x_ + (size_t)warp * NFEAT;
    float p = 0.f;
    for (int j = lane; j < NFEAT; j += 32) p = fmaf(row[j], lw[j], p);
    #pragma unroll
    for (int off = 16; off; off >>= 1) p += __shfl_xor_sync(0xffffffffu, p, off);
    if (lane == 0) g_xm[warp] = p;
}

// ---------------- per-step prep ------------------------------------------------
__global__ void k_prep(const float* __restrict__ sp, const float* __restrict__ out, int step) {
    __shared__ float smax[1024];
    int tid = threadIdx.x;
    float lam = 1.f / (1.f + __expf(-sp[0]));
    float lmax = -CUDART_INF_F;
    for (int b = tid; b < BATCH; b += 1024) {
        float I1v = step ? out[b]             : 0.f;
        float I2v = step ? out[2 * BATCH + b] : 0.f;
        float xmv = g_xm[b];
        g_x[b]  = (1.f - lam) * xmv + lam * I1v;
        float x2v = (1.f - lam) * xmv + lam * I2v;
        g_x2[b] = x2v;
        lmax = fmaxf(lmax, x2v);
    }
    smax[tid] = lmax;
    __syncthreads();
    for (int off = 512; off; off >>= 1) {
        if (tid < off) smax[tid] = fmaxf(smax[tid], smax[tid + off]);
        __syncthreads();
    }
    if (tid == 0) g_xfinal = smax[0] + 10.f;
}

// ---------------- 64->64 quarter-layer: thread = 4 evals x 16 neurons ----------
// Reads all 64 act rows (coalesced float4), accumulates own 16 neurons.
__device__ __forceinline__ void layer_q(const float* __restrict__ sWT,
                                        const float* __restrict__ sbias,
                                        const float* __restrict__ actCol, int qh,
                                        unsigned long long acc[4][8]) {
    #pragma unroll
    for (int jp = 0; jp < 8; ++jp) {
        unsigned long long bp = *(const unsigned long long*)(sbias + qh * 16 + 2 * jp);
        acc[0][jp] = bp; acc[1][jp] = bp; acc[2][jp] = bp; acc[3][jp] = bp;
    }

    float4 apn = *(const float4*)(actCol);    // k=0

    #pragma unroll 2
    for (int k = 0; k < 64; ++k) {
        unsigned long long a2x = pack2(apn.x, apn.x);
        unsigned long long a2y = pack2(apn.y, apn.y);
        unsigned long long a2z = pack2(apn.z, apn.z);
        unsigned long long a2w = pack2(apn.w, apn.w);
        apn = *(const float4*)(actCol + (k + 1) * ACT_ROW);   // row 64 = pad

        const ulonglong2* w4 = (const ulonglong2*)(sWT + k * 64 + qh * 16);
        #pragma unroll
        for (int i = 0; i < 4; ++i) {
            ulonglong2 wv = w4[i];                 // warp-uniform broadcast LDS.128
            acc[0][2 * i]     = fma2(wv.x, a2x, acc[0][2 * i]);
            acc[0][2 * i + 1] = fma2(wv.y, a2x, acc[0][2 * i + 1]);
            acc[1][2 * i]     = fma2(wv.x, a2y, acc[1][2 * i]);
            acc[1][2 * i + 1] = fma2(wv.y, a2y, acc[1][2 * i + 1]);
            acc[2][2 * i]     = fma2(wv.x, a2z, acc[2][2 * i]);
            acc[2][2 * i + 1] = fma2(wv.y, a2z, acc[2][2 * i + 1]);
            acc[3][2 * i]     = fma2(wv.x, a2w, acc[3][2 * i]);
            acc[3][2 * i + 1] = fma2(wv.y, a2w, acc[3][2 * i + 1]);
        }
    }
}

// ReLU + transpose (eval-major acc -> row-major float4) + store own 16 rows.
__device__ __forceinline__ void store_q(float* __restrict__ actCol, int qh,
                                        unsigned long long acc[4][8]) {
    #pragma unroll
    for (int jp = 0; jp < 8; ++jp) {
        float lo0, hi0, lo1, hi1, lo2, hi2, lo3, hi3;
        unpack2(acc[0][jp], lo0, hi0);
        unpack2(acc[1][jp], lo1, hi1);
        unpack2(acc[2][jp], lo2, hi2);
        unpack2(acc[3][jp], lo3, hi3);
        float4 vl = make_float4(fmaxf(lo0, 0.f), fmaxf(lo1, 0.f),
                                fmaxf(lo2, 0.f), fmaxf(lo3, 0.f));
        float4 vh = make_float4(fmaxf(hi0, 0.f), fmaxf(hi1, 0.f),
                                fmaxf(hi2, 0.f), fmaxf(hi3, 0.f));
        *(float4*)(actCol + (qh * 16 + 2 * jp) * ACT_ROW)     = vl;
        *(float4*)(actCol + (qh * 16 + 2 * jp + 1) * ACT_ROW) = vh;
    }
}

// ---------------- eval kernel ----------------------------------------------------
template <int MODE>
__global__ void __launch_bounds__(TPB, 1) k_eval(
    const float* __restrict__ W0, const float* __restrict__ b0,
    const float* __restrict__ W1, const float* __restrict__ b1,
    const float* __restrict__ W2, const float* __restrict__ b2,
    const float* __restrict__ W3, const float* __restrict__ b3,
    const float* __restrict__ Wf, const float* __restrict__ h,
    float* __restrict__ out)
{
    extern __shared__ float sm[];
    const int tid = threadIdx.x;
    const int qh  = tid / QCOL;        // neuron quarter (3-warp granularity)
    const int col = tid - qh * QCOL;   // eval column

    // ---- cooperative fill ----
    for (int idx = tid; idx < 4096; idx += TPB) {
        int k = idx >> 6, j = idx & 63;
        sm[OFF_W1T + idx] = W1[j * 64 + k];
        sm[OFF_W2T + idx] = W2[j * 64 + k];
    }
    if (tid < 64) {
        #pragma unroll
        for (int d = 0; d < 5; ++d) sm[OFF_W0 + tid * 8 + d] = W0[tid * 5 + d];
        sm[OFF_W0 + tid * 8 + 5] = b0[tid];
        sm[OFF_B1 + tid] = b1[tid];
        sm[OFF_B2 + tid] = b2[tid];
        sm[OFF_W3 + tid] = W3[tid];
    }
    if (tid < 5)   sm[OFF_WF + tid] = Wf[tid];
    if (tid == 64) sm[OFF_B3] = b3[0];

    // ---- per-eval params: 4 consecutive evals per column ----
    constexpr int NS  = (MODE == 0) ? 52 : 51;
    constexpr int TOT = BATCH * NS;
    const int Ebase = (blockIdx.x * QCOL + col) * 4;

    float  X[4];
    int    row[4], slot[4];
    bool   valid[4];
    float4 hv[4];
    #pragma unroll
    for (int e = 0; e < 4; ++e) {
        int E = Ebase + e;
        valid[e] = (E < TOT);
        if (!valid[e]) E = 0;
        row[e]  = E / NS;
        slot[e] = E - row[e] * NS;
        float lo = (MODE == 0) ? 0.f : g_x2[row[e]];
        float hi = (MODE == 0) ? g_x[row[e]] : g_xfinal;
        int sc = (slot[e] < S51) ? slot[e] : 0;
        X[e] = lo + (hi - lo) * (g_ccs[sc] + 1.f) * 0.5f;
        if (MODE == 0 && slot[e] == S51) X[e] = g_x2[row[e]];
        hv[e] = ((const float4*)h)[row[e]];
    }

    __syncthreads();

    float* actCol = sm + OFF_ACT + 4 * col;

    // ---- layer 0: own 16 neurons for 4 evals ----
    #pragma unroll 4
    for (int j = 0; j < 16; ++j) {
        const float* w = sm + OFF_W0 + (qh * 16 + j) * 8;   // broadcast
        float w0 = w[0], w1 = w[1], w2 = w[2], w3v = w[3], w4 = w[4], bb = w[5];
        float4 v;
        v.x = fmaf(w0, X[0], bb); v.y = fmaf(w0, X[1], bb);
        v.z = fmaf(w0, X[2], bb); v.w = fmaf(w0, X[3], bb);
        v.x = fmaf(w1, hv[0].x, v.x); v.y = fmaf(w1, hv[1].x, v.y);
        v.z = fmaf(w1, hv[2].x, v.z); v.w = fmaf(w1, hv[3].x, v.w);
        v.x = fmaf(w2, hv[0].y, v.x); v.y = fmaf(w2, hv[1].y, v.y);
        v.z = fmaf(w2, hv[2].y, v.z); v.w = fmaf(w2, hv[3].y, v.w);
        v.x = fmaf(w3v, hv[0].z, v.x); v.y = fmaf(w3v, hv[1].z, v.y);
        v.z = fmaf(w3v, hv[2].z, v.z); v.w = fmaf(w3v, hv[3].z, v.w);
        v.x = fmaf(w4, hv[0].w, v.x); v.y = fmaf(w4, hv[1].w, v.y);
        v.z = fmaf(w4, hv[2].w, v.z); v.w = fmaf(w4, hv[3].w, v.w);
        v.x = fmaxf(v.x, 0.f); v.y = fmaxf(v.y, 0.f);
        v.z = fmaxf(v.z, 0.f); v.w = fmaxf(v.w, 0.f);
        *(float4*)(actCol + (qh * 16 + j) * ACT_ROW) = v;
    }
    __syncthreads();

    unsigned long long acc[4][8];

    // ---- layer 1 ----
    layer_q(sm + OFF_W1T, sm + OFF_B1, actCol, qh, acc);
    __syncthreads();                            // all reads done before overwrite
    store_q(actCol, qh, acc);
    __syncthreads();

    // ---- layer 2 ----
    layer_q(sm + OFF_W2T, sm + OFF_B2, actCol, qh, acc);
    __syncthreads();
    store_q(actCol, qh, acc);
    __syncthreads();

    // ---- layer 3: partial dot over own 16 rows ----
    float y0 = 0.f, y1 = 0.f, y2 = 0.f, y3 = 0.f;
    #pragma unroll
    for (int kk = 0; kk < 16; ++kk) {
        float4 ap = *(const float4*)(actCol + (qh * 16 + kk) * ACT_ROW);
        float w = sm[OFF_W3 + qh * 16 + kk];
        y0 = fmaf(w, ap.x, y0); y1 = fmaf(w, ap.y, y1);
        y2 = fmaf(w, ap.z, y2); y3 = fmaf(w, ap.w, y3);
    }
    *(float4*)(sm + OFF_PART + (qh * QCOL + col) * 4) = make_float4(y0, y1, y2, y3);
    __syncthreads();

    if (qh == 0) {
        float4 p1 = *(const float4*)(sm + OFF_PART + (QCOL + col) * 4);
        float4 p2 = *(const float4*)(sm + OFF_PART + (2 * QCOL + col) * 4);
        float4 p3 = *(const float4*)(sm + OFF_PART + (3 * QCOL + col) * 4);
        float b3v = sm[OFF_B3];
        float y[4];
        y[0] = y0 + p1.x + p2.x + p3.x + b3v;
        y[1] = y1 + p1.y + p2.y + p3.y + b3v;
        y[2] = y2 + p1.z + p2.z + p3.z + b3v;
        y[3] = y3 + p1.w + p2.w + p3.w + b3v;

        constexpr float P0 = (MODE == 0) ? 1.1f : 1.5f;
        constexpr float P1 = (MODE == 0) ? 1.1f : 2.0f;
        constexpr float P2 = (MODE == 0) ? 1.5f : 2.5f;
        constexpr float P3 = (MODE == 0) ? 2.0f : 3.0f;
        constexpr float P4 = (MODE == 0) ? 2.5f : 3.5f;
        const float wf0 = sm[OFF_WF + 0], wf1 = sm[OFF_WF + 1], wf2 = sm[OFF_WF + 2];
        const float wf3 = sm[OFF_WF + 3], wf4 = sm[OFF_WF + 4];

        #pragma unroll
        for (int e = 0; e < 4; ++e) {
            float z  = (y[e] > 0.f) ? (y[e] + 1.f) : __expf(y[e]);
            float lg = __log2f(z);
            float g = 0.f;
            g += __fdividef(wf0, exp2f(P0 * lg) + 1.f);
            g += __fdividef(wf1, exp2f(P1 * lg) + 1.f);
            g += __fdividef(wf2, exp2f(P2 * lg) + 1.f);
            g += __fdividef(wf3, exp2f(P3 * lg) + 1.f);
            g += __fdividef(wf4, exp2f(P4 * lg) + 1.f);
            float val = fmaxf(g, 0.f);

            if (valid[e]) {
                if (MODE == 0 && slot[e] == S51) out[BATCH + row[e]] = val;   // out_first
                else g_vals[MODE][row[e] * 52 + slot[e]] = g_ccw[slot[e]] * val;
            }
        }
    }
}

// ---------------- merged deterministic quadrature reduce -----------------------
__global__ void k_reduce(float* __restrict__ out) {
    const bool m0 = (blockIdx.x < BATCH / 8);
    int blk  = m0 ? blockIdx.x : blockIdx.x - BATCH / 8;
    int row  = blk * 8 + (threadIdx.x >> 5);
    int lane = threadIdx.x & 31;
    const float* v = (m0 ? g_vals[0] : g_vals[1]) + row * 52;
    float s = v[lane];
    if (lane < 19) s += v[32 + lane];
    #pragma unroll
    for (int off = 16; off; off >>= 1) s += __shfl_xor_sync(0xffffffffu, s, off);
    if (lane == 0) {
        if (m0) out[row]             = s * g_x[row] * 0.5f;
        else    out[2 * BATCH + row] = s * (g_xfinal - g_x2[row]) * 0.5f * ALPHA_INV;
    }
}

// ---------------- launch ---------------------------------------------------------
extern "C" void kernel_launch(void* const* d_in, const int* in_sizes, int n_in,
                              void* d_out, int out_size) {
    (void)in_sizes; (void)n_in; (void)out_size;
    const float* x_ = (const float*)d_in[0];
    const float* h_ = (const float*)d_in[1];
    const float* lw = (const float*)d_in[2];
    const float* sp = (const float*)d_in[3];
    const float* f1p[9] = { (const float*)d_in[4],  (const float*)d_in[5],
                            (const float*)d_in[6],  (const float*)d_in[7],
                            (const float*)d_in[8],  (const float*)d_in[9],
                            (const float*)d_in[10], (const float*)d_in[11],
                            (const float*)d_in[12] };
    const float* f2p[9] = { (const float*)d_in[13], (const float*)d_in[14],
                            (const float*)d_in[15], (const float*)d_in[16],
                            (const float*)d_in[17], (const float*)d_in[18],
                            (const float*)d_in[19], (const float*)d_in[20],
                            (const float*)d_in[21] };
    float* out = (float*)d_out;

    cudaFuncSetAttribute(k_eval<0>, cudaFuncAttributeMaxDynamicSharedMemorySize, SMEM_BYTES);
    cudaFuncSetAttribute(k_eval<1>, cudaFuncAttributeMaxDynamicSharedMemorySize, SMEM_BYTES);

    k_init_cc<<<S51, 64>>>();
    k_xm<<<BATCH / 8, 256>>>(x_, lw);

    for (int step = 0; step < 2; ++step) {
        k_prep<<<1, 1024>>>(sp, out, step);
        // MODE 0: 212992 evals / 384 per block -> 555 blocks (tail guarded)
        k_eval<0><<<555, TPB, SMEM_BYTES>>>(f1p[0], f1p[1], f1p[2], f1p[3], f1p[4],
                                            f1p[5], f1p[6], f1p[7], f1p[8], h_, out);
        // MODE 1: 208896 evals / 384 per block -> 544 blocks (exact)
        k_eval<1><<<544, TPB, SMEM_BYTES>>>(f2p[0], f2p[1], f2p[2], f2p[3], f2p[4],
                                            f2p[5], f2p[6], f2p[7], f2p[8], h_, out);
        k_reduce<<<2 * (BATCH / 8), 256>>>(out);
    }
}